// round 12
// baseline (speedup 1.0000x reference)
#include <cuda_runtime.h>
#include <cuda_bf16.h>
#include <math.h>

#define NSLOT 16
#define NCAND 96
#define NEG_INF (-3.4e38f)

// Scratch (__device__ globals)
__device__ float2        g_lst[4][NSLOT][1024]; // [head][slot][t]: (s_index_bits, e)
__device__ float         g_sum[4][1024];        // unnormalized softmax denominator
__device__ unsigned char g_cnt[1024][4];        // counts per (t, head)

// ---------------------------------------------------------------------------
// Kernel 1: per-head offset scores + per-row sparse softmax lists.
// 4 blocks (one per head) x 1024 threads (one per row t).
// ---------------------------------------------------------------------------
__global__ void __launch_bounds__(1024, 1)
k_scores(const float* __restrict__ embed,
         const float* __restrict__ inw,
         const float* __restrict__ qnw,
         const float* __restrict__ knw,
         const float* __restrict__ qp,
         const float* __restrict__ kp) {
    int h = blockIdx.x;
    int t = threadIdx.x;
    int lane = t & 31, warp = t >> 5;

    __shared__ float s_wm[32];
    __shared__ int   s_cnt;
    __shared__ int   s_cd[NCAND];
    __shared__ float s_cf[NCAND];

    if (t == 0) s_cnt = 0;

    // P, X from embed row 0 + weights (broadcast loads; token-independent
    // after head rms-norm)
    float P, X;
    {
        float e0 = embed[0], e1 = embed[1], e2 = embed[2];
        float vv = (e0 * e0 + e1 * e1 + e2 * e2) * (1.0f / 3.0f);
        float rr = rsqrtf(vv + 1e-6f);
        float xl0 = e0 * rr * inw[0], xl1 = e1 * rr * inw[1], xl2 = e2 * rr * inw[2];
        float k0 = kp[0] * xl0 + kp[1] * xl1 + kp[2] * xl2;
        float k1 = kp[3] * xl0 + kp[4] * xl1 + kp[5] * xl2;
        float rk = rsqrtf((k0 * k0 + k1 * k1) * 0.5f + 1e-6f);
        float kn0 = k0 * rk * knw[0], kn1 = k1 * rk * knw[1];
        const float* q0r = qp + (2 * h) * 3;
        const float* q1r = qp + (2 * h + 1) * 3;
        float q0 = q0r[0] * xl0 + q0r[1] * xl1 + q0r[2] * xl2;
        float q1 = q1r[0] * xl0 + q1r[1] * xl1 + q1r[2] * xl2;
        float rq = rsqrtf((q0 * q0 + q1 * q1) * 0.5f + 1e-6f);
        float qn0 = q0 * rq * qnw[0], qn1 = q1 * rq * qnw[1];
        P = (qn0 * kn0 + qn1 * kn1) * 0.70710678118654752f;
        X = (qn0 * kn1 - qn1 * kn0) * 0.70710678118654752f;
    }
    float cs, sn;
    sincosf((float)t, &sn, &cs);
    float f = P * cs + X * sn;   // score at offset delta = t

    // inclusive prefix-max scan (shfl warp scan + cross-warp combine)
    float m = f;
    #pragma unroll
    for (int off = 1; off < 32; off <<= 1) {
        float v = __shfl_up_sync(0xffffffffu, m, off);
        if (lane >= off) m = fmaxf(m, v);
    }
    if (lane == 31) s_wm[warp] = m;
    __syncthreads();
    if (warp == 0) {
        float wm = s_wm[lane];
        #pragma unroll
        for (int off = 1; off < 32; off <<= 1) {
            float v = __shfl_up_sync(0xffffffffu, wm, off);
            if (lane >= off) wm = fmaxf(wm, v);
        }
        s_wm[lane] = wm;
    }
    __syncthreads();
    float M = (warp == 0) ? m : fmaxf(m, s_wm[warp - 1]);

    // candidate pool: offsets within 13 of their prefix max
    if (f >= M - 13.0f) {
        int i = atomicAdd(&s_cnt, 1);
        if (i < NCAND) { s_cd[i] = t; s_cf[i] = f; }
    }
    __syncthreads();

    // per-row sparse softmax: store (s_index, e) unnormalized; sum separately
    int cn = min(s_cnt, NCAND);
    float thr = M - 13.0f;
    float sum = 0.0f;
    int n = 0;
    for (int j = 0; j < cn; j++) {
        int dj = s_cd[j];
        float fj = s_cf[j];
        if (dj <= t && fj > thr && n < NSLOT) {
            float e = __expf(fj - M);
            sum += e;
            g_lst[h][n][t] = make_float2(__int_as_float(t - dj), e);
            n++;
        }
    }
    g_sum[h][t] = sum;
    g_cnt[t][h] = (unsigned char)n;
}

// ---------------------------------------------------------------------------
// Kernel 2: 128 blocks x 1024 threads. block -> (b = blk>>3, chunk = blk&7).
// Thread = (token, head, half): 8 predicated independent list loads, octet
// shfl-reduce, epilogue. One barrier total.
// ---------------------------------------------------------------------------
__global__ void __launch_bounds__(1024, 1)
k_main(const int* __restrict__ tok,
       const float* __restrict__ embed,
       const float* __restrict__ inw,
       const float* __restrict__ vp,
       const float* __restrict__ postw,
       const float* __restrict__ finw,
       const float* __restrict__ op,
       const float* __restrict__ gp,
       const float* __restrict__ upw,
       const float* __restrict__ dp,
       float* __restrict__ out) {
    int tid = threadIdx.x;
    int b = blockIdx.x >> 3;
    int t0 = (blockIdx.x & 7) << 7;
    int t = t0 + (tid >> 3);
    int h = (tid >> 1) & 3;
    int half = tid & 1;
    int pr = tid & 7;

    __shared__ int    s_tok[1024];
    __shared__ float  s_emb[30];
    __shared__ float4 s_w[4][10];

    // stage token row (256 int4 over threads 0,4,8,...)
    if ((tid & 3) == 0) {
        const int4* rowv = (const int4*)(tok + b * 1024);
        ((int4*)s_tok)[tid >> 2] = rowv[tid >> 2];
    }
    if (tid < 30) s_emb[tid] = embed[tid];
    // folded v * o_proj table per (head, digit)
    if (tid >= 256 && tid < 296) {
        int q = tid - 256;
        int hh = q / 10, dd = q % 10;
        float e0 = embed[3 * dd], e1 = embed[3 * dd + 1], e2 = embed[3 * dd + 2];
        float vv = (e0 * e0 + e1 * e1 + e2 * e2) * (1.0f / 3.0f);
        float rr = rsqrtf(vv + 1e-6f);
        float y0 = e0 * rr * inw[0], y1 = e1 * rr * inw[1], y2 = e2 * rr * inw[2];
        float v0 = vp[0] * y0 + vp[1] * y1 + vp[2] * y2;
        float v1 = vp[3] * y0 + vp[4] * y1 + vp[5] * y2;
        float w0 = v0 * op[0 * 8 + 2 * hh] + v1 * op[0 * 8 + 2 * hh + 1];
        float w1 = v0 * op[1 * 8 + 2 * hh] + v1 * op[1 * 8 + 2 * hh + 1];
        float w2 = v0 * op[2 * 8 + 2 * hh] + v1 * op[2 * 8 + 2 * hh + 1];
        s_w[hh][dd] = make_float4(w0, w1, w2, 0.0f);
    }

    // independent global loads (no barrier needed): count, denominator
    int n = (int)g_cnt[t][h];
    float den = g_sum[h][t];

    __syncthreads();

    int d = s_tok[t];
    float x0 = s_emb[3 * d], x1 = s_emb[3 * d + 1], x2 = s_emb[3 * d + 2];

    // 8 predicated independent gather slots (j = 2*jj + half)
    float c0 = 0.0f, c1 = 0.0f, c2 = 0.0f;
    #pragma unroll
    for (int jj = 0; jj < 8; jj++) {
        int j = 2 * jj + half;
        if (j < n) {
            float2 e = g_lst[h][j][t];
            float4 w = s_w[h][s_tok[__float_as_int(e.x)]];
            c0 += e.y * w.x;
            c1 += e.y * w.y;
            c2 += e.y * w.z;
        }
    }
    // combine halves, normalize, combine heads (octet shfl tree)
    c0 += __shfl_xor_sync(0xffffffffu, c0, 1);
    c1 += __shfl_xor_sync(0xffffffffu, c1, 1);
    c2 += __shfl_xor_sync(0xffffffffu, c2, 1);
    float inv = 1.0f / den;
    c0 *= inv; c1 *= inv; c2 *= inv;
    #pragma unroll
    for (int off = 2; off < 8; off <<= 1) {
        c0 += __shfl_xor_sync(0xffffffffu, c0, off);
        c1 += __shfl_xor_sync(0xffffffffu, c1, off);
        c2 += __shfl_xor_sync(0xffffffffu, c2, off);
    }
    x0 += c0; x1 += c1; x2 += c2;

    // epilogue (redundant per octet; logits split across octet lanes)
    float var = (x0 * x0 + x1 * x1 + x2 * x2) * (1.0f / 3.0f);
    float r = rsqrtf(var + 1e-6f);
    float y0 = x0 * r * postw[0];
    float y1 = x1 * r * postw[1];
    float y2 = x2 * r * postw[2];
    #pragma unroll
    for (int j = 0; j < 4; j++) {
        float g = gp[j * 3] * y0 + gp[j * 3 + 1] * y1 + gp[j * 3 + 2] * y2;
        float u = upw[j * 3] * y0 + upw[j * 3 + 1] * y1 + upw[j * 3 + 2] * y2;
        float sil = g / (1.0f + __expf(-g));
        float hh = sil * u;
        x0 += dp[0 * 4 + j] * hh;
        x1 += dp[1 * 4 + j] * hh;
        x2 += dp[2 * 4 + j] * hh;
    }
    float var2 = (x0 * x0 + x1 * x1 + x2 * x2) * (1.0f / 3.0f);
    float r2 = rsqrtf(var2 + 1e-6f);
    float z0 = x0 * r2 * finw[0];
    float z1 = x1 * r2 * finw[1];
    float z2 = x2 * r2 * finw[2];

    if (pr < 5) {
        int da = 2 * pr, db = 2 * pr + 1;
        float la = z0 * s_emb[3 * da] + z1 * s_emb[3 * da + 1] + z2 * s_emb[3 * da + 2];
        float lb = z0 * s_emb[3 * db] + z1 * s_emb[3 * db + 1] + z2 * s_emb[3 * db + 2];
        float2* o2 = (float2*)(out + (size_t)(b * 1024 + t) * 10);
        o2[pr] = make_float2(la, lb);
    }
}

extern "C" void kernel_launch(void* const* d_in, const int* in_sizes, int n_in,
                              void* d_out, int out_size) {
    const int*   tok   = (const int*)d_in[0];
    const float* embed = (const float*)d_in[1];
    const float* inw   = (const float*)d_in[2];
    const float* postw = (const float*)d_in[3];
    const float* finw  = (const float*)d_in[4];
    const float* qnw   = (const float*)d_in[5];
    const float* knw   = (const float*)d_in[6];
    const float* kp    = (const float*)d_in[7];
    const float* vp    = (const float*)d_in[8];
    const float* qp    = (const float*)d_in[9];
    const float* op    = (const float*)d_in[10];
    const float* gp    = (const float*)d_in[11];
    const float* upw   = (const float*)d_in[12];
    const float* dp    = (const float*)d_in[13];
    float* out = (float*)d_out;

    k_scores<<<4, 1024>>>(embed, inw, qnw, knw, qp, kp);
    k_main<<<128, 1024>>>(tok, embed, inw, vp, postw, finw, op, gp, upw, dp, out);
}

// round 13
// speedup vs baseline: 1.2839x; 1.2839x over previous
#include <cuda_runtime.h>
#include <cuda_bf16.h>
#include <math.h>

#define PCAP 40
#define NEG_INF (-3.4e38f)

__device__ __constant__ float c_cos8[8] = {
    1.0f, 0.5403023058681398f, -0.4161468365471424f, -0.9899924966004454f,
    -0.6536436208636119f, 0.2836621854632263f, 0.9601702866503661f, 0.7539022543433046f
};
__device__ __constant__ float c_sin8[8] = {
    0.0f, 0.8414709848078965f, 0.9092974268256817f, 0.1411200080598672f,
    -0.7568024953079282f, -0.9589242746631385f, -0.27941549819892586f, 0.6569865987187891f
};

// 128 blocks x 512 threads. block -> (b = blk>>3, chunk = blk&7; 128 tokens).
// Phase 1: warp w -> head w&3, delta segment (w>>2)*256 + lane*8, 8/lane.
// Phase 2: thread = (token, head) quad; shfl-reduce heads.
__global__ void __launch_bounds__(512)
k_all(const int* __restrict__ tok,
      const float* __restrict__ embed,
      const float* __restrict__ inw,
      const float* __restrict__ postw,
      const float* __restrict__ finw,
      const float* __restrict__ qnw,
      const float* __restrict__ knw,
      const float* __restrict__ kp,
      const float* __restrict__ vp,
      const float* __restrict__ qp,
      const float* __restrict__ op,
      const float* __restrict__ gp,
      const float* __restrict__ upw,
      const float* __restrict__ dp,
      float* __restrict__ out) {
    int tid = threadIdx.x;
    int lane = tid & 31, wid = tid >> 5;
    int b = blockIdx.x >> 3;
    int chunk = blockIdx.x & 7;
    int t0 = chunk << 7;
    int tmax = t0 + 127;

    __shared__ int    s_tok[1024];
    __shared__ float  s_emb[30];
    __shared__ float4 s_w[4][10];
    __shared__ float2 s_pool[4][PCAP];
    __shared__ int    s_pn[4];
    __shared__ float  s_part[4][4];  // inclusive max of each 256-delta segment
    __shared__ float  s_half[4][4];  // inclusive max of first 128 of each segment

    // ---------- phase 0: staging (independent loads) ----------
    if (tid < 4) s_pn[tid] = 0;
    if (tid < 256) {
        const int4* rowv = (const int4*)(tok + b * 1024);
        ((int4*)s_tok)[tid] = rowv[tid];
    }
    if (tid < 30) s_emb[tid] = embed[tid];
    if (tid >= 256 && tid < 296) {
        int q = tid - 256;
        int hh = q / 10, dd = q % 10;
        float e0 = embed[3 * dd], e1 = embed[3 * dd + 1], e2 = embed[3 * dd + 2];
        float vv = (e0 * e0 + e1 * e1 + e2 * e2) * (1.0f / 3.0f);
        float rr = rsqrtf(vv + 1e-6f);
        float y0 = e0 * rr * inw[0], y1 = e1 * rr * inw[1], y2 = e2 * rr * inw[2];
        float v0 = vp[0] * y0 + vp[1] * y1 + vp[2] * y2;
        float v1 = vp[3] * y0 + vp[4] * y1 + vp[5] * y2;
        float w0 = v0 * op[0 * 8 + 2 * hh] + v1 * op[0 * 8 + 2 * hh + 1];
        float w1 = v0 * op[1 * 8 + 2 * hh] + v1 * op[1 * 8 + 2 * hh + 1];
        float w2 = v0 * op[2 * 8 + 2 * hh] + v1 * op[2 * 8 + 2 * hh + 1];
        s_w[hh][dd] = make_float4(w0, w1, w2, 0.0f);
    }

    // ---------- phase 1: score scan, 4 warps per head ----------
    int h1 = wid & 3;
    int part = wid >> 2;
    int base = part * 256 + lane * 8;

    float f8[8];
    {
        // P, X from embed row 0 + weights (broadcast loads)
        float e0 = embed[0], e1 = embed[1], e2 = embed[2];
        float vv = (e0 * e0 + e1 * e1 + e2 * e2) * (1.0f / 3.0f);
        float rr = rsqrtf(vv + 1e-6f);
        float xl0 = e0 * rr * inw[0], xl1 = e1 * rr * inw[1], xl2 = e2 * rr * inw[2];
        float k0 = kp[0] * xl0 + kp[1] * xl1 + kp[2] * xl2;
        float k1 = kp[3] * xl0 + kp[4] * xl1 + kp[5] * xl2;
        float rk = rsqrtf((k0 * k0 + k1 * k1) * 0.5f + 1e-6f);
        float kn0 = k0 * rk * knw[0], kn1 = k1 * rk * knw[1];
        const float* q0r = qp + (2 * h1) * 3;
        const float* q1r = qp + (2 * h1 + 1) * 3;
        float q0 = q0r[0] * xl0 + q0r[1] * xl1 + q0r[2] * xl2;
        float q1 = q1r[0] * xl0 + q1r[1] * xl1 + q1r[2] * xl2;
        float rq = rsqrtf((q0 * q0 + q1 * q1) * 0.5f + 1e-6f);
        float qn0 = q0 * rq * qnw[0], qn1 = q1 * rq * qnw[1];
        float P = (qn0 * kn0 + qn1 * kn1) * 0.70710678118654752f;
        float X = (qn0 * kn1 - qn1 * kn0) * 0.70710678118654752f;
        float cb, sb;
        sincosf((float)base, &sb, &cb);
        float A = P * cb + X * sb;
        float B = X * cb - P * sb;
        #pragma unroll
        for (int i = 0; i < 8; i++)
            f8[i] = A * c_cos8[i] + B * c_sin8[i];
    }
    // lane max + warp inclusive scan
    float lm = f8[0];
    #pragma unroll
    for (int i = 1; i < 8; i++) lm = fmaxf(lm, f8[i]);
    float sc = lm;
    #pragma unroll
    for (int off = 1; off < 32; off <<= 1) {
        float v = __shfl_up_sync(0xffffffffu, sc, off);
        if (lane >= off) sc = fmaxf(sc, v);
    }
    if (lane == 15) s_half[h1][part] = sc;   // covers first 128 deltas of segment
    if (lane == 31) s_part[h1][part] = sc;   // covers full 256-delta segment
    __syncthreads();

    // cross-warp exclusive prefix for this lane's run start
    {
        float wpre = NEG_INF;
        #pragma unroll
        for (int p = 0; p < 3; p++)
            if (p < part) wpre = fmaxf(wpre, s_part[h1][p]);
        float ex = __shfl_up_sync(0xffffffffu, sc, 1);
        float run = fmaxf((lane == 0) ? NEG_INF : ex, wpre);

        // M_low: exclusive prefix max at t0 (t0 = 128*chunk)
        int hc = chunk >> 1;                  // full 256-segments before t0
        float M_low = NEG_INF;
        #pragma unroll
        for (int p = 0; p < 3; p++)
            if (p < hc) M_low = fmaxf(M_low, s_part[h1][p]);
        if (chunk & 1) M_low = fmaxf(M_low, s_half[h1][hc]);

        if (base <= tmax) {
            #pragma unroll
            for (int i = 0; i < 8; i++) {
                float f = f8[i];
                if (f >= fmaxf(run, M_low) - 13.0f && base + i <= tmax) {
                    int idx = atomicAdd(&s_pn[h1], 1);
                    if (idx < PCAP)
                        s_pool[h1][idx] = make_float2((float)(base + i), f);
                }
                run = fmaxf(run, f);
            }
        }
    }
    __syncthreads();

    // ---------- phase 2: thread = (token, head); quad-reduce ----------
    int t = t0 + (tid >> 2);
    int h = tid & 3;
    int d = s_tok[t];
    float x0 = s_emb[3 * d], x1 = s_emb[3 * d + 1], x2 = s_emb[3 * d + 2];

    float cx0, cx1, cx2;
    {
        int n = min(s_pn[h], PCAP);
        float M = NEG_INF;
        for (int j = 0; j < n; j++) {
            float2 e = s_pool[h][j];
            if ((int)e.x <= t) M = fmaxf(M, e.y);
        }
        float thr = M - 13.0f;
        float sum = 0.0f, c0 = 0.0f, c1 = 0.0f, c2 = 0.0f;
        for (int j = 0; j < n; j++) {
            float2 e = s_pool[h][j];
            int dj = (int)e.x;
            if (dj <= t && e.y > thr) {
                float p = __expf(e.y - M);
                sum += p;
                float4 w = s_w[h][s_tok[t - dj]];
                c0 += p * w.x;
                c1 += p * w.y;
                c2 += p * w.z;
            }
        }
        float inv = 1.0f / sum;
        cx0 = c0 * inv;
        cx1 = c1 * inv;
        cx2 = c2 * inv;
    }
    #pragma unroll
    for (int off = 1; off < 4; off <<= 1) {
        cx0 += __shfl_xor_sync(0xffffffffu, cx0, off);
        cx1 += __shfl_xor_sync(0xffffffffu, cx1, off);
        cx2 += __shfl_xor_sync(0xffffffffu, cx2, off);
    }
    x0 += cx0;
    x1 += cx1;
    x2 += cx2;

    // ---------- epilogue (redundant per quad; stores split by lane) ----------
    float var = (x0 * x0 + x1 * x1 + x2 * x2) * (1.0f / 3.0f);
    float r = rsqrtf(var + 1e-6f);
    float y0 = x0 * r * postw[0];
    float y1 = x1 * r * postw[1];
    float y2 = x2 * r * postw[2];
    #pragma unroll
    for (int j = 0; j < 4; j++) {
        float g = gp[j * 3] * y0 + gp[j * 3 + 1] * y1 + gp[j * 3 + 2] * y2;
        float u = upw[j * 3] * y0 + upw[j * 3 + 1] * y1 + upw[j * 3 + 2] * y2;
        float sil = g / (1.0f + __expf(-g));
        float hh = sil * u;
        x0 += dp[0 * 4 + j] * hh;
        x1 += dp[1 * 4 + j] * hh;
        x2 += dp[2 * 4 + j] * hh;
    }
    float var2 = (x0 * x0 + x1 * x1 + x2 * x2) * (1.0f / 3.0f);
    float r2 = rsqrtf(var2 + 1e-6f);
    float z0 = x0 * r2 * finw[0];
    float z1 = x1 * r2 * finw[1];
    float z2 = x2 * r2 * finw[2];

    float* o = out + (size_t)(b * 1024 + t) * 10;
    {
        int da = 2 * h, db = 2 * h + 1;
        float la = z0 * s_emb[3 * da] + z1 * s_emb[3 * da + 1] + z2 * s_emb[3 * da + 2];
        float lb = z0 * s_emb[3 * db] + z1 * s_emb[3 * db + 1] + z2 * s_emb[3 * db + 2];
        ((float2*)o)[h] = make_float2(la, lb);
        if (h == 0) {
            float l8 = z0 * s_emb[24] + z1 * s_emb[25] + z2 * s_emb[26];
            float l9 = z0 * s_emb[27] + z1 * s_emb[28] + z2 * s_emb[29];
            ((float2*)o)[4] = make_float2(l8, l9);
        }
    }
}

extern "C" void kernel_launch(void* const* d_in, const int* in_sizes, int n_in,
                              void* d_out, int out_size) {
    const int*   tok   = (const int*)d_in[0];
    const float* embed = (const float*)d_in[1];
    const float* inw   = (const float*)d_in[2];
    const float* postw = (const float*)d_in[3];
    const float* finw  = (const float*)d_in[4];
    const float* qnw   = (const float*)d_in[5];
    const float* knw   = (const float*)d_in[6];
    const float* kp    = (const float*)d_in[7];
    const float* vp    = (const float*)d_in[8];
    const float* qp    = (const float*)d_in[9];
    const float* op    = (const float*)d_in[10];
    const float* gp    = (const float*)d_in[11];
    const float* upw   = (const float*)d_in[12];
    const float* dp    = (const float*)d_in[13];
    float* out = (float*)d_out;

    k_all<<<128, 512>>>(tok, embed, inw, postw, finw, qnw, knw,
                        kp, vp, qp, op, gp, upw, dp, out);
}

// round 14
// speedup vs baseline: 1.5837x; 1.2335x over previous
#include <cuda_runtime.h>
#include <cuda_bf16.h>
#include <math.h>

#define PCAP 40
#define NEG_INF (-3.4e38f)

__device__ __constant__ float c_cos8[8] = {
    1.0f, 0.5403023058681398f, -0.4161468365471424f, -0.9899924966004454f,
    -0.6536436208636119f, 0.2836621854632263f, 0.9601702866503661f, 0.7539022543433046f
};
__device__ __constant__ float c_sin8[8] = {
    0.0f, 0.8414709848078965f, 0.9092974268256817f, 0.1411200080598672f,
    -0.7568024953079282f, -0.9589242746631385f, -0.27941549819892586f, 0.6569865987187891f
};

// 128 blocks x 512 threads. block -> (b = blk>>3, chunk = blk&7; 128 tokens).
// Phase 1: warp w -> head w&3, delta segment (w>>2)*256 + lane*8, 8/lane.
// Phase 2: thread = (token, head) quad; shfl-reduce heads; MLP split per quad.
__global__ void __launch_bounds__(512)
k_all(const int* __restrict__ tok,
      const float* __restrict__ embed,
      const float* __restrict__ inw,
      const float* __restrict__ postw,
      const float* __restrict__ finw,
      const float* __restrict__ qnw,
      const float* __restrict__ knw,
      const float* __restrict__ kp,
      const float* __restrict__ vp,
      const float* __restrict__ qp,
      const float* __restrict__ op,
      const float* __restrict__ gp,
      const float* __restrict__ upw,
      const float* __restrict__ dp,
      float* __restrict__ out) {
    int tid = threadIdx.x;
    int lane = tid & 31, wid = tid >> 5;
    int b = blockIdx.x >> 3;
    int chunk = blockIdx.x & 7;
    int t0 = chunk << 7;
    int tmax = t0 + 127;

    __shared__ int    s_tok[1024];
    __shared__ float  s_emb[30];
    __shared__ float4 s_w[4][10];
    __shared__ float2 s_pool[4][PCAP];
    __shared__ int    s_pn[4];
    __shared__ float  s_part[4][4];  // inclusive max of each 256-delta segment
    __shared__ float  s_half[4][4];  // inclusive max of first 128 of each segment

    // ---------- phase 0: staging (independent loads) ----------
    if (tid < 4) s_pn[tid] = 0;
    if (tid < 256) {
        const int4* rowv = (const int4*)(tok + b * 1024);
        ((int4*)s_tok)[tid] = rowv[tid];
    }
    if (tid < 30) s_emb[tid] = embed[tid];
    if (tid >= 256 && tid < 296) {
        int q = tid - 256;
        int hh = q / 10, dd = q % 10;
        float e0 = embed[3 * dd], e1 = embed[3 * dd + 1], e2 = embed[3 * dd + 2];
        float vv = (e0 * e0 + e1 * e1 + e2 * e2) * (1.0f / 3.0f);
        float rr = rsqrtf(vv + 1e-6f);
        float y0 = e0 * rr * inw[0], y1 = e1 * rr * inw[1], y2 = e2 * rr * inw[2];
        float v0 = vp[0] * y0 + vp[1] * y1 + vp[2] * y2;
        float v1 = vp[3] * y0 + vp[4] * y1 + vp[5] * y2;
        float w0 = v0 * op[0 * 8 + 2 * hh] + v1 * op[0 * 8 + 2 * hh + 1];
        float w1 = v0 * op[1 * 8 + 2 * hh] + v1 * op[1 * 8 + 2 * hh + 1];
        float w2 = v0 * op[2 * 8 + 2 * hh] + v1 * op[2 * 8 + 2 * hh + 1];
        s_w[hh][dd] = make_float4(w0, w1, w2, 0.0f);
    }

    // ---------- phase 1: score scan, 4 warps per head ----------
    int h1 = wid & 3;
    int part = wid >> 2;
    int base = part * 256 + lane * 8;

    float f8[8];
    {
        float e0 = embed[0], e1 = embed[1], e2 = embed[2];
        float vv = (e0 * e0 + e1 * e1 + e2 * e2) * (1.0f / 3.0f);
        float rr = rsqrtf(vv + 1e-6f);
        float xl0 = e0 * rr * inw[0], xl1 = e1 * rr * inw[1], xl2 = e2 * rr * inw[2];
        float k0 = kp[0] * xl0 + kp[1] * xl1 + kp[2] * xl2;
        float k1 = kp[3] * xl0 + kp[4] * xl1 + kp[5] * xl2;
        float rk = rsqrtf((k0 * k0 + k1 * k1) * 0.5f + 1e-6f);
        float kn0 = k0 * rk * knw[0], kn1 = k1 * rk * knw[1];
        const float* q0r = qp + (2 * h1) * 3;
        const float* q1r = qp + (2 * h1 + 1) * 3;
        float q0 = q0r[0] * xl0 + q0r[1] * xl1 + q0r[2] * xl2;
        float q1 = q1r[0] * xl0 + q1r[1] * xl1 + q1r[2] * xl2;
        float rq = rsqrtf((q0 * q0 + q1 * q1) * 0.5f + 1e-6f);
        float qn0 = q0 * rq * qnw[0], qn1 = q1 * rq * qnw[1];
        float P = (qn0 * kn0 + qn1 * kn1) * 0.70710678118654752f;
        float X = (qn0 * kn1 - qn1 * kn0) * 0.70710678118654752f;
        float cb, sb;
        sincosf((float)base, &sb, &cb);
        float A = P * cb + X * sb;
        float B = X * cb - P * sb;
        #pragma unroll
        for (int i = 0; i < 8; i++)
            f8[i] = A * c_cos8[i] + B * c_sin8[i];
    }
    float lm = f8[0];
    #pragma unroll
    for (int i = 1; i < 8; i++) lm = fmaxf(lm, f8[i]);
    float sc = lm;
    #pragma unroll
    for (int off = 1; off < 32; off <<= 1) {
        float v = __shfl_up_sync(0xffffffffu, sc, off);
        if (lane >= off) sc = fmaxf(sc, v);
    }
    if (lane == 15) s_half[h1][part] = sc;
    if (lane == 31) s_part[h1][part] = sc;
    __syncthreads();

    {
        float wpre = NEG_INF;
        #pragma unroll
        for (int p = 0; p < 3; p++)
            if (p < part) wpre = fmaxf(wpre, s_part[h1][p]);
        float ex = __shfl_up_sync(0xffffffffu, sc, 1);
        float run = fmaxf((lane == 0) ? NEG_INF : ex, wpre);

        int hc = chunk >> 1;
        float M_low = NEG_INF;
        #pragma unroll
        for (int p = 0; p < 3; p++)
            if (p < hc) M_low = fmaxf(M_low, s_part[h1][p]);
        if (chunk & 1) M_low = fmaxf(M_low, s_half[h1][hc]);

        if (base <= tmax) {
            #pragma unroll
            for (int i = 0; i < 8; i++) {
                float f = f8[i];
                if (f >= fmaxf(run, M_low) - 13.0f && base + i <= tmax) {
                    int idx = atomicAdd(&s_pn[h1], 1);
                    if (idx < PCAP)
                        s_pool[h1][idx] = make_float2(__int_as_float(base + i), f);
                }
                run = fmaxf(run, f);
            }
        }
    }
    __syncthreads();

    // ---------- phase 2: thread = (token, head); quad-reduce ----------
    int t = t0 + (tid >> 2);
    int h = tid & 3;
    int d = s_tok[t];
    float x0 = s_emb[3 * d], x1 = s_emb[3 * d + 1], x2 = s_emb[3 * d + 2];

    float cx0, cx1, cx2;
    {
        int n = min(s_pn[h], PCAP);
        float M = NEG_INF;
        #pragma unroll 2
        for (int j = 0; j < n; j++) {
            float2 e = s_pool[h][j];
            if (__float_as_int(e.x) <= t) M = fmaxf(M, e.y);
        }
        float thr = M - 13.0f;
        float sum = 0.0f, c0 = 0.0f, c1 = 0.0f, c2 = 0.0f;
        #pragma unroll 2
        for (int j = 0; j < n; j++) {
            float2 e = s_pool[h][j];
            int dj = __float_as_int(e.x);
            if (dj <= t && e.y > thr) {
                float p = __expf(e.y - M);
                sum += p;
                float4 w = s_w[h][s_tok[t - dj]];
                c0 += p * w.x;
                c1 += p * w.y;
                c2 += p * w.z;
            }
        }
        float inv = 1.0f / sum;
        cx0 = c0 * inv;
        cx1 = c1 * inv;
        cx2 = c2 * inv;
    }
    #pragma unroll
    for (int off = 1; off < 4; off <<= 1) {
        cx0 += __shfl_xor_sync(0xffffffffu, cx0, off);
        cx1 += __shfl_xor_sync(0xffffffffu, cx1, off);
        cx2 += __shfl_xor_sync(0xffffffffu, cx2, off);
    }
    x0 += cx0;
    x1 += cx1;
    x2 += cx2;

    // ---------- epilogue: post-norm; MLP split across quad; final + logits ---
    float var = (x0 * x0 + x1 * x1 + x2 * x2) * (1.0f / 3.0f);
    float r = rsqrtf(var + 1e-6f);
    float y0 = x0 * r * postw[0];
    float y1 = x1 * r * postw[1];
    float y2 = x2 * r * postw[2];
    // each quad lane computes MLP channel j = h
    float d0, d1, d2;
    {
        int j = h;
        float g = gp[j * 3] * y0 + gp[j * 3 + 1] * y1 + gp[j * 3 + 2] * y2;
        float u = upw[j * 3] * y0 + upw[j * 3 + 1] * y1 + upw[j * 3 + 2] * y2;
        float sil = g / (1.0f + __expf(-g));
        float hh = sil * u;
        d0 = dp[0 * 4 + j] * hh;
        d1 = dp[1 * 4 + j] * hh;
        d2 = dp[2 * 4 + j] * hh;
    }
    #pragma unroll
    for (int off = 1; off < 4; off <<= 1) {
        d0 += __shfl_xor_sync(0xffffffffu, d0, off);
        d1 += __shfl_xor_sync(0xffffffffu, d1, off);
        d2 += __shfl_xor_sync(0xffffffffu, d2, off);
    }
    x0 += d0;
    x1 += d1;
    x2 += d2;

    float var2 = (x0 * x0 + x1 * x1 + x2 * x2) * (1.0f / 3.0f);
    float r2 = rsqrtf(var2 + 1e-6f);
    float z0 = x0 * r2 * finw[0];
    float z1 = x1 * r2 * finw[1];
    float z2 = x2 * r2 * finw[2];

    float* o = out + (size_t)(b * 1024 + t) * 10;
    {
        int da = 2 * h, db = 2 * h + 1;
        float la = z0 * s_emb[3 * da] + z1 * s_emb[3 * da + 1] + z2 * s_emb[3 * da + 2];
        float lb = z0 * s_emb[3 * db] + z1 * s_emb[3 * db + 1] + z2 * s_emb[3 * db + 2];
        ((float2*)o)[h] = make_float2(la, lb);
        if (h == 0) {
            float l8 = z0 * s_emb[24] + z1 * s_emb[25] + z2 * s_emb[26];
            float l9 = z0 * s_emb[27] + z1 * s_emb[28] + z2 * s_emb[29];
            ((float2*)o)[4] = make_float2(l8, l9);
        }
    }
}

extern "C" void kernel_launch(void* const* d_in, const int* in_sizes, int n_in,
                              void* d_out, int out_size) {
    const int*   tok   = (const int*)d_in[0];
    const float* embed = (const float*)d_in[1];
    const float* inw   = (const float*)d_in[2];
    const float* postw = (const float*)d_in[3];
    const float* finw  = (const float*)d_in[4];
    const float* qnw   = (const float*)d_in[5];
    const float* knw   = (const float*)d_in[6];
    const float* kp    = (const float*)d_in[7];
    const float* vp    = (const float*)d_in[8];
    const float* qp    = (const float*)d_in[9];
    const float* op    = (const float*)d_in[10];
    const float* gp    = (const float*)d_in[11];
    const float* upw   = (const float*)d_in[12];
    const float* dp    = (const float*)d_in[13];
    float* out = (float*)d_out;

    k_all<<<128, 512>>>(tok, embed, inw, postw, finw, qnw, knw,
                        kp, vp, qp, op, gp, upw, dp, out);
}